// round 13
// baseline (speedup 1.0000x reference)
#include <cuda_runtime.h>
#include <cuda_fp16.h>

#define B 8
#define S 512
#define E 64
#define H 8

// smem layout (bytes), static 32.8KB
#define K_OFF   0            // K fp16 [512][8], 16B rows
#define VP_OFF  8192         // Vp fp16 [512][24], 48B rows: cols0-7=V, col8=1, 9-15=0
#define SM_BYTES (8192 + 512*48)   // 32768
// finalizer overlay
#define WF_ROW  65
// Wsm floats [64*65] at offset 0 (16640B), bias at 16640

__device__ float    g_ctx[B * S * E];   // [4096][64]
__device__ unsigned g_cnt[32];          // per (b, qchunk) arrival counters

__device__ __forceinline__ unsigned smem_u32(const void* p) {
    unsigned a;
    asm("{ .reg .u64 t; cvta.to.shared.u64 t, %1; cvt.u32.u64 %0, t; }" : "=r"(a) : "l"(p));
    return a;
}

__global__ void __launch_bounds__(256, 4) qmha_kernel(
    const float* __restrict__ x,      // [B, S, E]
    const float* __restrict__ theta,  // [8]
    const float* __restrict__ W,      // [64, 64] (e, k)
    const float* __restrict__ bo,     // [64]
    float* __restrict__ out)          // [4096, 64]
{
    __shared__ __align__(16) char sm[SM_BYTES];
    __shared__ unsigned fin_flag;

    const int tid = threadIdx.x;      // 0..255
    const int bid = blockIdx.x;       // 0..255
    const int b  = bid >> 5;
    const int h  = (bid >> 2) & 7;
    const int qc = bid & 3;           // 128-query chunk

    float th[8];
#pragma unroll
    for (int j = 0; j < 8; ++j) th[j] = __ldg(theta + j);

    __half* Ksm = (__half*)(sm + K_OFF);    // [s][8]
    __half* Vp  = (__half*)(sm + VP_OFF);   // [s][24]

    // ---------------- Phase A: build K / Vp fp16 for this head ----------------
#pragma unroll
    for (int rr = 0; rr < 2; ++rr) {
        const int s = tid + rr * 256;
        const float* xr = x + ((size_t)(b * S + s)) * E + h * 8;
        float4 v0 = __ldg((const float4*)xr);
        float4 v1 = __ldg((const float4*)xr + 1);
        float c0 = __cosf(v0.x + th[0]);
        float c1 = __cosf(v0.y + th[1]);
        float c2 = __cosf(v0.z + th[2]);
        float c3 = __cosf(v0.w + th[3]);
        float c4 = __cosf(v1.x + th[4]);
        float c5 = __cosf(v1.y + th[5]);
        float c6 = __cosf(v1.z + th[6]);
        float c7 = __cosf(v1.w + th[7]);
        float q1 = c0 * c1, q2 = q1 * c2, q3 = q2 * c3;
        float q4 = q3 * c4, q5 = q4 * c5, q6 = q5 * c6, q7 = q6 * c7;
        float q0 = c1 * c2 * c3 * c4 * c5 * c6 * c7;
        __half2 h01 = __floats2half2_rn(q0, q1);
        __half2 h23 = __floats2half2_rn(q2, q3);
        __half2 h45 = __floats2half2_rn(q4, q5);
        __half2 h67 = __floats2half2_rn(q6, q7);
        uint4 kv = make_uint4(*(unsigned*)&h01, *(unsigned*)&h23,
                              *(unsigned*)&h45, *(unsigned*)&h67);
        *(uint4*)(Ksm + s * 8)  = kv;
        *(uint4*)(Vp  + s * 24) = kv;                              // cols 0-7
        *(uint4*)(Vp + s * 24 + 8) = make_uint4(0x00003C00u, 0u, 0u, 0u); // col8=1
    }
    __syncthreads();

    // ---------------- Phase B: FA2-style mma chain ----------------
    const int w = tid >> 5;           // warp = q-tile
    const int l = tid & 31;
    const int qrow = qc * 128 + w * 16;

    const unsigned kbaseS = smem_u32(Ksm);
    const unsigned vbaseS = smem_u32(Vp);

    // A frags: Q[16x8] from Ksm rows qrow..qrow+15, scaled by (1/sqrt8)*log2e
    unsigned a0, a1;
    {
        unsigned aaddr = kbaseS + (qrow + (l & 15)) * 16;
        asm volatile("ldmatrix.sync.aligned.m8n8.x2.shared.b16 {%0,%1}, [%2];"
                     : "=r"(a0), "=r"(a1) : "r"(aaddr));
        const __half2 sch = __float2half2_rn(0.51010202f);
        __half2 t0 = __hmul2(*(__half2*)&a0, sch);
        __half2 t1 = __hmul2(*(__half2*)&a1, sch);
        a0 = *(unsigned*)&t0;
        a1 = *(unsigned*)&t1;
    }

    float o0 = 0.f, o1 = 0.f, o2 = 0.f, o3 = 0.f;   // cols 0-7 (ctx dims)
    float o4 = 0.f, o5 = 0.f, o6 = 0.f, o7 = 0.f;   // cols 8-15 (col8 = denom)
    const float fz = 0.f;

    const unsigned kaddr0 = kbaseS + l * 16;  // lane -> key within 32-key chunk
    const unsigned vaddr0 = vbaseS + (((l >> 4) & 1) * 8 + (l & 7)) * 48
                                   + ((l >> 3) & 1) * 16;

    for (int c = 0; c < 16; ++c) {            // 32 keys per chunk
        unsigned kb0, kb1, kb2, kb3;
        asm volatile("ldmatrix.sync.aligned.m8n8.x4.shared.b16 {%0,%1,%2,%3}, [%4];"
                     : "=r"(kb0), "=r"(kb1), "=r"(kb2), "=r"(kb3)
                     : "r"(kaddr0 + c * 512));
        unsigned vb0, vb1, vb2, vb3, vb4, vb5, vb6, vb7;
        asm volatile("ldmatrix.sync.aligned.m8n8.x4.trans.shared.b16 {%0,%1,%2,%3}, [%4];"
                     : "=r"(vb0), "=r"(vb1), "=r"(vb2), "=r"(vb3)
                     : "r"(vaddr0 + c * 1536));
        asm volatile("ldmatrix.sync.aligned.m8n8.x4.trans.shared.b16 {%0,%1,%2,%3}, [%4];"
                     : "=r"(vb4), "=r"(vb5), "=r"(vb6), "=r"(vb7)
                     : "r"(vaddr0 + c * 1536 + 768));

#pragma unroll
        for (int t = 0; t < 4; ++t) {
            unsigned kb = (t == 0) ? kb0 : (t == 1) ? kb1 : (t == 2) ? kb2 : kb3;
            unsigned vlo = (t == 0) ? vb0 : (t == 1) ? vb2 : (t == 2) ? vb4 : vb6;
            unsigned vhi = (t == 0) ? vb1 : (t == 1) ? vb3 : (t == 2) ? vb5 : vb7;
            float d0, d1, d2, d3;
            asm volatile("mma.sync.aligned.m16n8k8.row.col.f32.f16.f16.f32 "
                         "{%0,%1,%2,%3}, {%4,%5}, {%6}, {%7,%8,%9,%10};"
                         : "=f"(d0), "=f"(d1), "=f"(d2), "=f"(d3)
                         : "r"(a0), "r"(a1), "r"(kb),
                           "f"(fz), "f"(fz), "f"(fz), "f"(fz));
            unsigned p0, p1;
            asm volatile("cvt.rn.f16x2.f32 %0, %1, %2;" : "=r"(p0) : "f"(d1), "f"(d0));
            asm volatile("cvt.rn.f16x2.f32 %0, %1, %2;" : "=r"(p1) : "f"(d3), "f"(d2));
            asm volatile("ex2.approx.f16x2 %0, %1;" : "=r"(p0) : "r"(p0));
            asm volatile("ex2.approx.f16x2 %0, %1;" : "=r"(p1) : "r"(p1));
            asm volatile("mma.sync.aligned.m16n8k8.row.col.f32.f16.f16.f32 "
                         "{%0,%1,%2,%3}, {%4,%5}, {%6}, {%0,%1,%2,%3};"
                         : "+f"(o0), "+f"(o1), "+f"(o2), "+f"(o3)
                         : "r"(p0), "r"(p1), "r"(vlo));
            asm volatile("mma.sync.aligned.m16n8k8.row.col.f32.f16.f16.f32 "
                         "{%0,%1,%2,%3}, {%4,%5}, {%6}, {%0,%1,%2,%3};"
                         : "+f"(o4), "+f"(o5), "+f"(o6), "+f"(o7)
                         : "r"(p0), "r"(p1), "r"(vhi));
        }
    }

    // epilogue: denom = col 8 (lanes with l%4==0 hold it); broadcast in 4-lane groups
    {
        float dlo = __shfl_sync(0xffffffffu, o4, l & 28);
        float dhi = __shfl_sync(0xffffffffu, o6, l & 28);
        float ilo, ihi;
        asm("rcp.approx.f32 %0, %1;" : "=f"(ilo) : "f"(dlo));
        asm("rcp.approx.f32 %0, %1;" : "=f"(ihi) : "f"(dhi));
        const int r = l >> 2, cc = (l & 3) * 2;
        const int n0 = b * S + qrow;
        *(float2*)(g_ctx + (size_t)(n0 + r) * 64 + h * 8 + cc) =
            make_float2(o0 * ilo, o1 * ilo);
        *(float2*)(g_ctx + (size_t)(n0 + r + 8) * 64 + h * 8 + cc) =
            make_float2(o2 * ihi, o3 * ihi);
    }

    // ---------------- arrival counter: 8th head-block finalizes ----------------
    __threadfence();
    __syncthreads();
    if (tid == 0) {
        unsigned v = atomicAdd(&g_cnt[b * 4 + qc], 1u);
        fin_flag = (v == 7u);
    }
    __syncthreads();
    if (!fin_flag) return;
    __threadfence();   // acquire: other blocks' g_ctx stores

    // ---------------- finalizer: projection of 128 rows ----------------
    float* Wsm = (float*)sm;                   // overlay (Ksm dead)
    float* bsm = (float*)(sm + 64 * WF_ROW * 4);
    for (int i = tid; i < 64 * 64; i += 256) {
        int e = i >> 6, k = i & 63;
        Wsm[e * WF_ROW + k] = __ldg(W + i);
    }
    if (tid < 64) bsm[tid] = __ldg(bo + tid);
    __syncthreads();

    const int n0 = b * S + qc * 128;
#pragma unroll 2
    for (int j = 0; j < 16; ++j) {
        const int r = w * 16 + j;
        const float4* crow = (const float4*)(g_ctx + (size_t)(n0 + r) * 64);
        float acc0 = bsm[l];
        float acc1 = bsm[l + 32];
#pragma unroll
        for (int k4 = 0; k4 < 16; ++k4) {
            float4 cv = __ldg(crow + k4);      // lane-uniform: 1-line broadcast
            const int k = k4 * 4;
            acc0 = fmaf(cv.x, Wsm[l * WF_ROW + k + 0], acc0);
            acc0 = fmaf(cv.y, Wsm[l * WF_ROW + k + 1], acc0);
            acc0 = fmaf(cv.z, Wsm[l * WF_ROW + k + 2], acc0);
            acc0 = fmaf(cv.w, Wsm[l * WF_ROW + k + 3], acc0);
            acc1 = fmaf(cv.x, Wsm[(l + 32) * WF_ROW + k + 0], acc1);
            acc1 = fmaf(cv.y, Wsm[(l + 32) * WF_ROW + k + 1], acc1);
            acc1 = fmaf(cv.z, Wsm[(l + 32) * WF_ROW + k + 2], acc1);
            acc1 = fmaf(cv.w, Wsm[(l + 32) * WF_ROW + k + 3], acc1);
        }
        out[(size_t)(n0 + r) * 64 + l]      = acc0;
        out[(size_t)(n0 + r) * 64 + l + 32] = acc1;
    }

    if (tid == 0) g_cnt[b * 4 + qc] = 0;   // reset for next graph replay
}

extern "C" void kernel_launch(void* const* d_in, const int* in_sizes, int n_in,
                              void* d_out, int out_size)
{
    const float* x     = (const float*)d_in[0];  // [8, 512, 64]
    const float* theta = (const float*)d_in[1];  // [8]
    const float* W_o   = (const float*)d_in[2];  // [64, 64]
    const float* b_o   = (const float*)d_in[3];  // [64]
    float* out = (float*)d_out;

    qmha_kernel<<<256, 256>>>(x, theta, W_o, b_o, out);
}

// round 14
// speedup vs baseline: 1.1247x; 1.1247x over previous
#include <cuda_runtime.h>
#include <cuda_fp16.h>

#define S 512
#define E 64
#define KB_STRIDE 48           // bytes per 2-key block in smem (bank-spread pad)

__device__ float    g_ctx[8 * S * E];   // [4096][64]
__device__ unsigned g_cnt[128];         // per (b, 32q-chunk) arrival counters

union SmU {
    char K[256 * KB_STRIDE];                         // 12288 B
    struct { float Ws[64 * 65]; float bs[64]; } p;   // proj overlay
};

__device__ __forceinline__ unsigned h2u(__half2 h) { return *reinterpret_cast<unsigned*>(&h); }
__device__ __forceinline__ __half2 u2h(unsigned u) { return *reinterpret_cast<__half2*>(&u); }
__device__ __forceinline__ __half2 h2ex2(__half2 v) {
    unsigned r, a = h2u(v);
    asm("ex2.approx.f16x2 %0, %1;" : "=r"(r) : "r"(a));
    return u2h(r);
}

__device__ __forceinline__ void cos_row8(const float* xr, const float* th, float* q) {
    float4 v0 = __ldg((const float4*)xr);
    float4 v1 = __ldg((const float4*)xr + 1);
    float c0 = __cosf(v0.x + th[0]);
    float c1 = __cosf(v0.y + th[1]);
    float c2 = __cosf(v0.z + th[2]);
    float c3 = __cosf(v0.w + th[3]);
    float c4 = __cosf(v1.x + th[4]);
    float c5 = __cosf(v1.y + th[5]);
    float c6 = __cosf(v1.z + th[6]);
    float c7 = __cosf(v1.w + th[7]);
    q[1] = c0 * c1; q[2] = q[1] * c2; q[3] = q[2] * c3;
    q[4] = q[3] * c4; q[5] = q[4] * c5; q[6] = q[5] * c6; q[7] = q[6] * c7;
    q[0] = c1 * c2 * c3 * c4 * c5 * c6 * c7;
}

// ---------------------------------------------------------------------------
// 1024 blocks x 128 thr: block = (b, h, 32-query chunk). 7 blocks/SM = 1 wave.
// Phase A: build fp16 K, KEY-PAIR packed: half2 = (key 2i, key 2i+1) per dim.
// Phase B: attention; thread = (query pair, g=0..7). Per 2 keys: one dot chain
//          per query yields both scores; one ex2 serves both keys.
// Counters: 8th head-block per (b,chunk) projects 32 rows (W overlay, pad-65).
// ---------------------------------------------------------------------------
__global__ void __launch_bounds__(128, 7) qmha_kernel(
    const float* __restrict__ x,      // [8, 512, 64]
    const float* __restrict__ theta,  // [8]
    const float* __restrict__ W,      // [64, 64] (e, k)
    const float* __restrict__ bo,     // [64]
    float* __restrict__ out)          // [4096, 64]
{
    __shared__ SmU sm;
    __shared__ unsigned fin_flag;

    const int tid = threadIdx.x;      // 0..127
    const int bid = blockIdx.x;       // 0..1023
    const int gid = bid >> 3;         // (b, qc) group
    const int h   = bid & 7;
    const int b   = gid >> 4;
    const int qc  = gid & 15;         // 32-query chunk

    float th[8];
#pragma unroll
    for (int j = 0; j < 8; ++j) th[j] = __ldg(theta + j);

    // ---- Phase A: build key-pair-packed fp16 K for this (b,h) ----
#pragma unroll
    for (int kk = 0; kk < 2; ++kk) {
        const int kb = tid + kk * 128;            // 2-key block 0..255
        const float* xr = x + ((size_t)(b * S + 2 * kb)) * E + h * 8;
        float ra[8], rb[8];
        cos_row8(xr, th, ra);                     // key 2kb
        cos_row8(xr + E, th, rb);                 // key 2kb+1
        __half2 p0 = __floats2half2_rn(ra[0], rb[0]);
        __half2 p1 = __floats2half2_rn(ra[1], rb[1]);
        __half2 p2 = __floats2half2_rn(ra[2], rb[2]);
        __half2 p3 = __floats2half2_rn(ra[3], rb[3]);
        __half2 p4 = __floats2half2_rn(ra[4], rb[4]);
        __half2 p5 = __floats2half2_rn(ra[5], rb[5]);
        __half2 p6 = __floats2half2_rn(ra[6], rb[6]);
        __half2 p7 = __floats2half2_rn(ra[7], rb[7]);
        char* dst = sm.K + kb * KB_STRIDE;
        *(uint4*)(dst)      = make_uint4(h2u(p0), h2u(p1), h2u(p2), h2u(p3));
        *(uint4*)(dst + 16) = make_uint4(h2u(p4), h2u(p5), h2u(p6), h2u(p7));
    }
    __syncthreads();

    // ---- Phase B: attention ----
    // tid = qp*8 + g : query pair qp (0..15) -> queries q0, q0+16; g (0..7).
    const int qp = tid >> 3;
    const int g  = tid & 7;
    const int r0 = qc * 32 + qp;      // query row A
    const int r1 = r0 + 16;           // query row B

    const __half2 sch2 = __float2half2_rn(0.51010202f); // (1/sqrt8)*log2e
    __half2 qs0[8], qs1[8];
    {
        const __half* Kh = (const __half*)sm.K;
#pragma unroll
        for (int d = 0; d < 8; ++d) {
            qs0[d] = __hmul2(__half2half2(Kh[(r0 >> 1) * 24 + d * 2 + (r0 & 1)]), sch2);
            qs1[d] = __hmul2(__half2half2(Kh[(r1 >> 1) * 24 + d * 2 + (r1 & 1)]), sch2);
        }
    }

    float F0[8] = {0,0,0,0,0,0,0,0}, F1[8] = {0,0,0,0,0,0,0,0};
    float lf0 = 0.f, lf1 = 0.f;
    const __half2 hz = __float2half2_rn(0.f);

    const char* base = sm.K + g * KB_STRIDE;     // kb = 8*t + g
    for (int o = 0; o < 4; ++o) {
        __half2 a0[8], a1[8];
#pragma unroll
        for (int d = 0; d < 8; ++d) { a0[d] = hz; a1[d] = hz; }
        __half2 l0 = hz, l1 = hz;
        const char* po = base + o * (64 * KB_STRIDE);
#pragma unroll
        for (int u = 0; u < 8; ++u) {            // 8 kb = 16 keys per chunk
            const char* p = po + u * (8 * KB_STRIDE);
            uint4 A  = *(const uint4*)(p);       // dims 0-3, keys (2i,2i+1)
            uint4 Bv = *(const uint4*)(p + 16);  // dims 4-7
            __half2 k0 = u2h(A.x),  k1 = u2h(A.y),  k2 = u2h(A.z),  k3 = u2h(A.w);
            __half2 k4 = u2h(Bv.x), k5 = u2h(Bv.y), k6 = u2h(Bv.z), k7 = u2h(Bv.w);
            // scores for both keys at once, per query
            __half2 s0 = __hmul2(qs0[0], k0);
            s0 = __hfma2(qs0[1], k1, s0);
            s0 = __hfma2(qs0[2], k2, s0);
            s0 = __hfma2(qs0[3], k3, s0);
            s0 = __hfma2(qs0[4], k4, s0);
            s0 = __hfma2(qs0[5], k5, s0);
            s0 = __hfma2(qs0[6], k6, s0);
            s0 = __hfma2(qs0[7], k7, s0);
            __half2 s1 = __hmul2(qs1[0], k0);
            s1 = __hfma2(qs1[1], k1, s1);
            s1 = __hfma2(qs1[2], k2, s1);
            s1 = __hfma2(qs1[3], k3, s1);
            s1 = __hfma2(qs1[4], k4, s1);
            s1 = __hfma2(qs1[5], k5, s1);
            s1 = __hfma2(qs1[6], k6, s1);
            s1 = __hfma2(qs1[7], k7, s1);
            __half2 w0 = h2ex2(s0);              // (w_q0k2i, w_q0k2i+1)
            __half2 w1 = h2ex2(s1);
            l0 = __hadd2(l0, w0);
            l1 = __hadd2(l1, w1);
            a0[0] = __hfma2(w0, k0, a0[0]);
            a0[1] = __hfma2(w0, k1, a0[1]);
            a0[2] = __hfma2(w0, k2, a0[2]);
            a0[3] = __hfma2(w0, k3, a0[3]);
            a0[4] = __hfma2(w0, k4, a0[4]);
            a0[5] = __hfma2(w0, k5, a0[5]);
            a0[6] = __hfma2(w0, k6, a0[6]);
            a0[7] = __hfma2(w0, k7, a0[7]);
            a1[0] = __hfma2(w1, k0, a1[0]);
            a1[1] = __hfma2(w1, k1, a1[1]);
            a1[2] = __hfma2(w1, k2, a1[2]);
            a1[3] = __hfma2(w1, k3, a1[3]);
            a1[4] = __hfma2(w1, k4, a1[4]);
            a1[5] = __hfma2(w1, k5, a1[5]);
            a1[6] = __hfma2(w1, k6, a1[6]);
            a1[7] = __hfma2(w1, k7, a1[7]);
        }
        // promote 16-key chunk to fp32 (sum both key-parity halves)
#pragma unroll
        for (int d = 0; d < 8; ++d) {
            float2 t0 = __half22float2(a0[d]); F0[d] += t0.x + t0.y;
            float2 t1 = __half22float2(a1[d]); F1[d] += t1.x + t1.y;
        }
        float2 tl0 = __half22float2(l0); lf0 += tl0.x + tl0.y;
        float2 tl1 = __half22float2(l1); lf1 += tl1.x + tl1.y;
    }

    // reduce across the 8 g-lanes (contiguous)
    float red[18];
#pragma unroll
    for (int d = 0; d < 8; ++d) { red[d] = F0[d]; red[8 + d] = F1[d]; }
    red[16] = lf0;
    red[17] = lf1;
#pragma unroll
    for (int v = 0; v < 18; ++v) {
        red[v] += __shfl_xor_sync(0xffffffffu, red[v], 1);
        red[v] += __shfl_xor_sync(0xffffffffu, red[v], 2);
        red[v] += __shfl_xor_sync(0xffffffffu, red[v], 4);
    }

    if (g == 0) {
        float i0 = 1.f / red[16];
        float i1 = 1.f / red[17];
        float* c0 = g_ctx + ((size_t)(b * S + r0)) * E + h * 8;
        *(float4*)(c0 + 0) = make_float4(red[0] * i0, red[1] * i0, red[2] * i0, red[3] * i0);
        *(float4*)(c0 + 4) = make_float4(red[4] * i0, red[5] * i0, red[6] * i0, red[7] * i0);
        float* c1 = g_ctx + ((size_t)(b * S + r1)) * E + h * 8;
        *(float4*)(c1 + 0) = make_float4(red[8] * i1, red[9] * i1, red[10] * i1, red[11] * i1);
        *(float4*)(c1 + 4) = make_float4(red[12] * i1, red[13] * i1, red[14] * i1, red[15] * i1);
    }

    // ---- arrival counter: 8th head-block per (b,qc) projects ----
    __threadfence();
    __syncthreads();
    if (tid == 0) {
        unsigned v = atomicAdd(&g_cnt[gid], 1u);
        fin_flag = (v == 7u);
    }
    __syncthreads();
    if (!fin_flag) return;
    __threadfence();                 // acquire other blocks' g_ctx stores

    // ---- finalizer: project 32 rows (overlay W into smem, pad-65) ----
    for (int i = tid; i < 1024; i += 128) {
        float4 w = __ldg((const float4*)W + i);
        int e = i >> 4, k = (i & 15) * 4;
        float* pp = &sm.p.Ws[e * 65 + k];
        pp[0] = w.x; pp[1] = w.y; pp[2] = w.z; pp[3] = w.w;
    }
    if (tid < 64) sm.p.bs[tid] = __ldg(bo + tid);
    __syncthreads();

    const int wrp  = tid >> 5;
    const int lane = tid & 31;
#pragma unroll 2
    for (int j = 0; j < 8; ++j) {
        const int n = b * S + qc * 32 + wrp * 8 + j;
        const float4* crow = (const float4*)(g_ctx + (size_t)n * 64);
        float A0 = sm.p.bs[lane];
        float A1 = sm.p.bs[lane + 32];
#pragma unroll
        for (int k4 = 0; k4 < 16; ++k4) {
            float4 cv = __ldg(crow + k4);        // lane-uniform broadcast
            const int k = k4 * 4;
            A0 = fmaf(cv.x, sm.p.Ws[lane * 65 + k + 0], A0);
            A0 = fmaf(cv.y, sm.p.Ws[lane * 65 + k + 1], A0);
            A0 = fmaf(cv.z, sm.p.Ws[lane * 65 + k + 2], A0);
            A0 = fmaf(cv.w, sm.p.Ws[lane * 65 + k + 3], A0);
            A1 = fmaf(cv.x, sm.p.Ws[(lane + 32) * 65 + k + 0], A1);
            A1 = fmaf(cv.y, sm.p.Ws[(lane + 32) * 65 + k + 1], A1);
            A1 = fmaf(cv.z, sm.p.Ws[(lane + 32) * 65 + k + 2], A1);
            A1 = fmaf(cv.w, sm.p.Ws[(lane + 32) * 65 + k + 3], A1);
        }
        out[(size_t)n * 64 + lane]      = A0;
        out[(size_t)n * 64 + lane + 32] = A1;
    }

    if (tid == 0) g_cnt[gid] = 0;    // reset for next graph replay
}

extern "C" void kernel_launch(void* const* d_in, const int* in_sizes, int n_in,
                              void* d_out, int out_size)
{
    const float* x     = (const float*)d_in[0];  // [8, 512, 64]
    const float* theta = (const float*)d_in[1];  // [8]
    const float* W_o   = (const float*)d_in[2];  // [64, 64]
    const float* b_o   = (const float*)d_in[3];  // [64]
    float* out = (float*)d_out;

    qmha_kernel<<<1024, 128>>>(x, theta, W_o, b_o, out);
}

// round 15
// speedup vs baseline: 2.0073x; 1.7848x over previous
#include <cuda_runtime.h>
#include <cuda_fp16.h>

#define B 8
#define S 512
#define E 64
#define H 8

// ---- dynamic smem layout (bytes) ------------------------------------------
#define KS_STRIDE 8208                 // per-head: 512*16B rows + 16B pad
#define KS_BYTES  (8 * KS_STRIDE)      // 65664
#define WS_OFF    KS_BYTES
#define WS_ROW    65                   // pad-65: scalar LDS banks (e+k)%32
#define WS_BYTES  (64 * WS_ROW * 4)    // 16640
#define CS_OFF    (WS_OFF + WS_BYTES)
#define CS_ROW    68                   // 16B-aligned float4 stores
#define CS_BYTES  (16 * CS_ROW * 4)    // 4352
#define BS_OFF    (CS_OFF + CS_BYTES)
#define SMEM_TOTAL (BS_OFF + 256)      // 86912 -> 2 blocks/SM

__device__ __forceinline__ unsigned h2u(__half2 h) { return *reinterpret_cast<unsigned*>(&h); }
__device__ __forceinline__ __half2 u2h(unsigned u) { return *reinterpret_cast<__half2*>(&u); }

__device__ __forceinline__ __half2 h2ex2(__half2 v) {
    unsigned r, a = h2u(v);
    asm("ex2.approx.f16x2 %0, %1;" : "=r"(r) : "r"(a));
    return u2h(r);
}

// ---------------------------------------------------------------------------
// One kernel: block = (b, 16-query chunk), all 8 heads. 256 blocks x 512 thr.
// Phase B processes TWO independent key streams per thread (keys 4i+g from
// the low 256 and high 256 keys) -> 2x ILP at the latency equilibrium.
// ---------------------------------------------------------------------------
__global__ void __launch_bounds__(512) fused_kernel(
    const float* __restrict__ x,      // [B, S, E]
    const float* __restrict__ theta,  // [8]
    const float* __restrict__ W,      // [64, 64] (e, k)
    const float* __restrict__ bo,     // [64]
    float* __restrict__ out)          // [B*S, 64]
{
    extern __shared__ char sm[];
    float* Ws = (float*)(sm + WS_OFF);
    float* Cs = (float*)(sm + CS_OFF);
    float* bs = (float*)(sm + BS_OFF);

    const int tid   = threadIdx.x;    // 0..511
    const int bid   = blockIdx.x;     // 0..255
    const int b     = bid >> 5;
    const int chunk = bid & 31;       // 16-query chunk

    // ---- stage W (pad-65 scalar) + bias ----
    for (int i = tid; i < 64 * 64; i += 512) {
        int e = i >> 6, k = i & 63;
        Ws[e * WS_ROW + k] = __ldg(W + i);
    }
    if (tid < 64) bs[tid] = __ldg(bo + tid);

    float th[8];
#pragma unroll
    for (int j = 0; j < 8; ++j) th[j] = __ldg(theta + j);

    // ---- Phase A: build fp16 K for all 8 heads ----
    const float4* x4 = (const float4*)x + (size_t)b * (S * E / 4);
#pragma unroll
    for (int j = 0; j < 16; ++j) {
        int m = j * 512 + tid;        // 0..8191
        int r = m >> 4;               // key row 0..511
        int c = m & 15;               // float4 chunk; head = c>>1
        float4 v = __ldg(x4 + m);
        int tb = (c & 1) * 4;
        float f0 = __cosf(v.x + th[tb + 0]);
        float f1 = __cosf(v.y + th[tb + 1]);
        float f2 = __cosf(v.z + th[tb + 2]);
        float f3 = __cosf(v.w + th[tb + 3]);
        float g0 = __shfl_xor_sync(0xffffffffu, f0, 1);
        float g1 = __shfl_xor_sync(0xffffffffu, f1, 1);
        float g2 = __shfl_xor_sync(0xffffffffu, f2, 1);
        float g3 = __shfl_xor_sync(0xffffffffu, f3, 1);
        bool hi = (c & 1);
        float c0 = hi ? g0 : f0, c1 = hi ? g1 : f1;
        float c2 = hi ? g2 : f2, c3 = hi ? g3 : f3;
        float c4 = hi ? f0 : g0, c5 = hi ? f1 : g1;
        float c6 = hi ? f2 : g2, c7 = hi ? f3 : g3;
        float q1 = c0 * c1, q2 = q1 * c2, q3 = q2 * c3;
        float q4 = q3 * c4, q5 = q4 * c5, q6 = q5 * c6, q7 = q6 * c7;
        float t01 = c1 * c2, t23 = c3 * c4, t45 = c5 * c6;
        float q0 = t01 * t23 * t45 * c7;
        float a0 = hi ? q4 : q0, a1 = hi ? q5 : q1;
        float a2 = hi ? q6 : q2, a3 = hi ? q7 : q3;
        __half2 p0 = __floats2half2_rn(a0, a1);
        __half2 p1 = __floats2half2_rn(a2, a3);
        char* dst = sm + (c >> 1) * KS_STRIDE + r * 16 + (c & 1) * 8;
        *(uint2*)dst = make_uint2(h2u(p0), h2u(p1));
    }
    __syncthreads();

    // ---- Phase B: attention, dual key streams ----
    // tid = h*64 + qq*4 + g : head h, query qq (0..15), key-split g (0..3).
    const int h  = tid >> 6;
    const int rr = tid & 63;
    const int qq = rr >> 2;
    const int g  = rr & 3;
    const int sq = chunk * 16 + qq;   // query's key-row index

    uint4 qv = *(const uint4*)(sm + h * KS_STRIDE + sq * 16);
    const __half2 sch = __float2half2_rn(0.51010202f); // (1/sqrt(8))*log2(e)
    __half2 qh0 = __hmul2(u2h(qv.x), sch);
    __half2 qh1 = __hmul2(u2h(qv.y), sch);
    __half2 qh2 = __hmul2(u2h(qv.z), sch);
    __half2 qh3 = __hmul2(u2h(qv.w), sch);

    const __half2 hz = __float2half2_rn(0.f);
    float F[8] = {0.f, 0.f, 0.f, 0.f, 0.f, 0.f, 0.f, 0.f};
    float lf = 0.f;

    const char* kpA = sm + h * KS_STRIDE + g * 16;   // keys 4i+g, i in [0,64)
    const char* kpB = kpA + 256 * 16;                // keys 256 + 4i+g
    for (int o = 0; o < 4; ++o) {
        __half2 aA0 = hz, aA1 = hz, aA2 = hz, aA3 = hz, lA = hz;
        __half2 aB0 = hz, aB1 = hz, aB2 = hz, aB3 = hz, lB = hz;
        const char* poA = kpA + o * 1024;            // 16 keys * 64B
        const char* poB = kpB + o * 1024;
#pragma unroll
        for (int i = 0; i < 16; ++i) {
            uint4 kva = *(const uint4*)(poA + i * 64);
            uint4 kvb = *(const uint4*)(poB + i * 64);
            // --- stream A ---
            {
                __half2 k0 = u2h(kva.x), k1 = u2h(kva.y), k2 = u2h(kva.z), k3 = u2h(kva.w);
                __half2 d = __hmul2(qh0, k0);
                d = __hfma2(qh1, k1, d);
                d = __hfma2(qh2, k2, d);
                d = __hfma2(qh3, k3, d);
                __half2 ds = __hadd2(d, __lowhigh2highlow(d));
                __half2 w2 = h2ex2(ds);
                lA = __hadd2(lA, w2);
                aA0 = __hfma2(w2, k0, aA0);
                aA1 = __hfma2(w2, k1, aA1);
                aA2 = __hfma2(w2, k2, aA2);
                aA3 = __hfma2(w2, k3, aA3);
            }
            // --- stream B (independent chain) ---
            {
                __half2 k0 = u2h(kvb.x), k1 = u2h(kvb.y), k2 = u2h(kvb.z), k3 = u2h(kvb.w);
                __half2 d = __hmul2(qh0, k0);
                d = __hfma2(qh1, k1, d);
                d = __hfma2(qh2, k2, d);
                d = __hfma2(qh3, k3, d);
                __half2 ds = __hadd2(d, __lowhigh2highlow(d));
                __half2 w2 = h2ex2(ds);
                lB = __hadd2(lB, w2);
                aB0 = __hfma2(w2, k0, aB0);
                aB1 = __hfma2(w2, k1, aB1);
                aB2 = __hfma2(w2, k2, aB2);
                aB3 = __hfma2(w2, k3, aB3);
            }
        }
        float2 t;
        t = __half22float2(aA0); F[0] += t.x; F[1] += t.y;
        t = __half22float2(aA1); F[2] += t.x; F[3] += t.y;
        t = __half22float2(aA2); F[4] += t.x; F[5] += t.y;
        t = __half22float2(aA3); F[6] += t.x; F[7] += t.y;
        lf += __low2float(lA);
        t = __half22float2(aB0); F[0] += t.x; F[1] += t.y;
        t = __half22float2(aB1); F[2] += t.x; F[3] += t.y;
        t = __half22float2(aB2); F[4] += t.x; F[5] += t.y;
        t = __half22float2(aB3); F[6] += t.x; F[7] += t.y;
        lf += __low2float(lB);
    }

    // reduce across the 4 split lanes (contiguous within the warp)
    float FF[9] = {F[0], F[1], F[2], F[3], F[4], F[5], F[6], F[7], lf};
#pragma unroll
    for (int v = 0; v < 9; ++v) {
        FF[v] += __shfl_xor_sync(0xffffffffu, FF[v], 1);
        FF[v] += __shfl_xor_sync(0xffffffffu, FF[v], 2);
    }

    if (g == 0) {
        float inv = 1.f / FF[8];
        float* cp = Cs + qq * CS_ROW + h * 8;
        *(float4*)(cp + 0) = make_float4(FF[0] * inv, FF[1] * inv, FF[2] * inv, FF[3] * inv);
        *(float4*)(cp + 4) = make_float4(FF[4] * inv, FF[5] * inv, FF[6] * inv, FF[7] * inv);
    }
    __syncthreads();

    // ---- Phase C: projection. out[n,e] = sum_k ctx[n,k]*W[e,k] + b[e] ----
    {
        const int q2   = tid >> 5;        // 0..15
        const int lane = tid & 31;
        const float* crow = Cs + q2 * CS_ROW;
        float acc0 = bs[lane];
        float acc1 = bs[lane + 32];
#pragma unroll 8
        for (int k = 0; k < 64; ++k) {
            float c = crow[k];                        // broadcast
            acc0 = fmaf(c, Ws[lane * WS_ROW + k], acc0);
            acc1 = fmaf(c, Ws[(lane + 32) * WS_ROW + k], acc1);
        }
        const int n = b * S + chunk * 16 + q2;
        out[(size_t)n * 64 + lane]      = acc0;
        out[(size_t)n * 64 + lane + 32] = acc1;
    }
}

extern "C" void kernel_launch(void* const* d_in, const int* in_sizes, int n_in,
                              void* d_out, int out_size)
{
    const float* x     = (const float*)d_in[0];  // [8, 512, 64]
    const float* theta = (const float*)d_in[1];  // [8]
    const float* W_o   = (const float*)d_in[2];  // [64, 64]
    const float* b_o   = (const float*)d_in[3];  // [64]
    float* out = (float*)d_out;

    cudaFuncSetAttribute(fused_kernel,
                         cudaFuncAttributeMaxDynamicSharedMemorySize, SMEM_TOTAL);
    fused_kernel<<<256, 512, SMEM_TOTAL>>>(x, theta, W_o, b_o, out);
}

// round 16
// speedup vs baseline: 2.1173x; 1.0548x over previous
#include <cuda_runtime.h>
#include <cuda_fp16.h>

#define B 8
#define S 512
#define E 64
#define H 8

// ---- dynamic smem layout (bytes) ------------------------------------------
// Phases A/B: K only. Phase C overlays W/bias/Cs onto the (dead) K region.
#define KS_STRIDE 8208                 // per-head: 512*16B rows + 16B pad
#define KS_BYTES  (8 * KS_STRIDE)      // 65664  -> 3 blocks/SM
#define WS_OFF    0                    // overlay: W at 0 (pad-65 scalar rows)
#define WS_ROW    65
#define BS_OFF    (64 * WS_ROW * 4)    // 16640
#define CS_OFF    (BS_OFF + 256)       // 16896 (16B aligned)
#define CS_ROW    68
#define SMEM_TOTAL KS_BYTES

__device__ __forceinline__ unsigned h2u(__half2 h) { return *reinterpret_cast<unsigned*>(&h); }
__device__ __forceinline__ __half2 u2h(unsigned u) { return *reinterpret_cast<__half2*>(&u); }

__device__ __forceinline__ __half2 h2ex2(__half2 v) {
    unsigned r, a = h2u(v);
    asm("ex2.approx.f16x2 %0, %1;" : "=r"(r) : "r"(a));
    return u2h(r);
}

// ---------------------------------------------------------------------------
// One kernel: block = (b, 16-query chunk), all 8 heads. 256 blocks x 512 thr.
// smem = K only during the main loop -> 3 blocks/SM, 48 warps/SM (was 32).
// Projection staging overlays the K region after phase B.
// ---------------------------------------------------------------------------
__global__ void __launch_bounds__(512, 3) fused_kernel(
    const float* __restrict__ x,      // [B, S, E]
    const float* __restrict__ theta,  // [8]
    const float* __restrict__ W,      // [64, 64] (e, k)
    const float* __restrict__ bo,     // [64]
    float* __restrict__ out)          // [B*S, 64]
{
    extern __shared__ char sm[];

    const int tid   = threadIdx.x;    // 0..511
    const int bid   = blockIdx.x;     // 0..255
    const int b     = bid >> 5;
    const int chunk = bid & 31;       // 16-query chunk

    float th[8];
#pragma unroll
    for (int j = 0; j < 8; ++j) th[j] = __ldg(theta + j);

    // ---- Phase A: build fp16 K for all 8 heads ----
    const float4* x4 = (const float4*)x + (size_t)b * (S * E / 4);
#pragma unroll
    for (int j = 0; j < 16; ++j) {
        int m = j * 512 + tid;        // 0..8191
        int r = m >> 4;               // key row 0..511
        int c = m & 15;               // float4 chunk; head = c>>1
        float4 v = __ldg(x4 + m);
        int tb = (c & 1) * 4;
        float f0 = __cosf(v.x + th[tb + 0]);
        float f1 = __cosf(v.y + th[tb + 1]);
        float f2 = __cosf(v.z + th[tb + 2]);
        float f3 = __cosf(v.w + th[tb + 3]);
        float g0 = __shfl_xor_sync(0xffffffffu, f0, 1);
        float g1 = __shfl_xor_sync(0xffffffffu, f1, 1);
        float g2 = __shfl_xor_sync(0xffffffffu, f2, 1);
        float g3 = __shfl_xor_sync(0xffffffffu, f3, 1);
        bool hi = (c & 1);
        float c0 = hi ? g0 : f0, c1 = hi ? g1 : f1;
        float c2 = hi ? g2 : f2, c3 = hi ? g3 : f3;
        float c4 = hi ? f0 : g0, c5 = hi ? f1 : g1;
        float c6 = hi ? f2 : g2, c7 = hi ? f3 : g3;
        float q1 = c0 * c1, q2 = q1 * c2, q3 = q2 * c3;
        float q4 = q3 * c4, q5 = q4 * c5, q6 = q5 * c6, q7 = q6 * c7;
        float t01 = c1 * c2, t23 = c3 * c4, t45 = c5 * c6;
        float q0 = t01 * t23 * t45 * c7;
        float a0 = hi ? q4 : q0, a1 = hi ? q5 : q1;
        float a2 = hi ? q6 : q2, a3 = hi ? q7 : q3;
        __half2 p0 = __floats2half2_rn(a0, a1);
        __half2 p1 = __floats2half2_rn(a2, a3);
        char* dst = sm + (c >> 1) * KS_STRIDE + r * 16 + (c & 1) * 8;
        *(uint2*)dst = make_uint2(h2u(p0), h2u(p1));
    }
    __syncthreads();

    // ---- Phase B: attention ----
    // tid = h*64 + qq*4 + g : head h, query qq (0..15), key-split g (0..3).
    const int h  = tid >> 6;
    const int rr = tid & 63;
    const int qq = rr >> 2;
    const int g  = rr & 3;
    const int sq = chunk * 16 + qq;   // query's key-row index

    uint4 qv = *(const uint4*)(sm + h * KS_STRIDE + sq * 16);
    const __half2 sch = __float2half2_rn(0.51010202f); // (1/sqrt(8))*log2(e)
    __half2 qh0 = __hmul2(u2h(qv.x), sch);
    __half2 qh1 = __hmul2(u2h(qv.y), sch);
    __half2 qh2 = __hmul2(u2h(qv.z), sch);
    __half2 qh3 = __hmul2(u2h(qv.w), sch);

    const __half2 hz = __float2half2_rn(0.f);
    float F[8] = {0.f, 0.f, 0.f, 0.f, 0.f, 0.f, 0.f, 0.f};
    float lf = 0.f;

    const char* kp = sm + h * KS_STRIDE + g * 16;   // keys s = 4i + g
    for (int o = 0; o < 8; ++o) {
        __half2 a0 = hz, a1 = hz, a2 = hz, a3 = hz, l2 = hz;
        const char* kpo = kp + o * 1024;            // 16 keys * 64B
#pragma unroll
        for (int i = 0; i < 16; ++i) {
            uint4 kv = *(const uint4*)(kpo + i * 64);
            __half2 k0 = u2h(kv.x), k1 = u2h(kv.y), k2 = u2h(kv.z), k3 = u2h(kv.w);
            __half2 d = __hmul2(qh0, k0);
            d = __hfma2(qh1, k1, d);
            d = __hfma2(qh2, k2, d);
            d = __hfma2(qh3, k3, d);
            __half2 ds = __hadd2(d, __lowhigh2highlow(d));
            __half2 w2 = h2ex2(ds);
            l2 = __hadd2(l2, w2);
            a0 = __hfma2(w2, k0, a0);
            a1 = __hfma2(w2, k1, a1);
            a2 = __hfma2(w2, k2, a2);
            a3 = __hfma2(w2, k3, a3);
        }
        float2 t;
        t = __half22float2(a0); F[0] += t.x; F[1] += t.y;
        t = __half22float2(a1); F[2] += t.x; F[3] += t.y;
        t = __half22float2(a2); F[4] += t.x; F[5] += t.y;
        t = __half22float2(a3); F[6] += t.x; F[7] += t.y;
        lf += __low2float(l2);
    }

    // reduce across the 4 split lanes (contiguous within the warp)
    float FF[9] = {F[0], F[1], F[2], F[3], F[4], F[5], F[6], F[7], lf};
#pragma unroll
    for (int v = 0; v < 9; ++v) {
        FF[v] += __shfl_xor_sync(0xffffffffu, FF[v], 1);
        FF[v] += __shfl_xor_sync(0xffffffffu, FF[v], 2);
    }

    // ---- K region is dead after this sync; overlay proj staging ----
    __syncthreads();

    float* Ws = (float*)(sm + WS_OFF);
    float* bs = (float*)(sm + BS_OFF);
    float* Cs = (float*)(sm + CS_OFF);

    if (g == 0) {
        float inv = 1.f / FF[8];
        float* cp = Cs + qq * CS_ROW + h * 8;
        *(float4*)(cp + 0) = make_float4(FF[0] * inv, FF[1] * inv, FF[2] * inv, FF[3] * inv);
        *(float4*)(cp + 4) = make_float4(FF[4] * inv, FF[5] * inv, FF[6] * inv, FF[7] * inv);
    }
    // stage W (pad-65 scalar) + bias concurrently with Cs writes
    for (int i = tid; i < 64 * 64; i += 512) {
        int e = i >> 6, k = i & 63;
        Ws[e * WS_ROW + k] = __ldg(W + i);
    }
    if (tid < 64) bs[tid] = __ldg(bo + tid);
    __syncthreads();

    // ---- Phase C: projection. out[n,e] = sum_k ctx[n,k]*W[e,k] + b[e] ----
    {
        const int q2   = tid >> 5;        // 0..15
        const int lane = tid & 31;
        const float* crow = Cs + q2 * CS_ROW;
        float acc0 = bs[lane];
        float acc1 = bs[lane + 32];
#pragma unroll 8
        for (int k = 0; k < 64; ++k) {
            float c = crow[k];                        // broadcast
            acc0 = fmaf(c, Ws[lane * WS_ROW + k], acc0);
            acc1 = fmaf(c, Ws[(lane + 32) * WS_ROW + k], acc1);
        }
        const int n = b * S + chunk * 16 + q2;
        out[(size_t)n * 64 + lane]      = acc0;
        out[(size_t)n * 64 + lane + 32] = acc1;
    }
}

extern "C" void kernel_launch(void* const* d_in, const int* in_sizes, int n_in,
                              void* d_out, int out_size)
{
    const float* x     = (const float*)d_in[0];  // [8, 512, 64]
    const float* theta = (const float*)d_in[1];  // [8]
    const float* W_o   = (const float*)d_in[2];  // [64, 64]
    const float* b_o   = (const float*)d_in[3];  // [64]
    float* out = (float*)d_out;

    cudaFuncSetAttribute(fused_kernel,
                         cudaFuncAttributeMaxDynamicSharedMemorySize, SMEM_TOTAL);
    fused_kernel<<<256, 512, SMEM_TOTAL>>>(x, theta, W_o, b_o, out);
}